// round 7
// baseline (speedup 1.0000x reference)
#include <cuda_runtime.h>
#include <cuda_bf16.h>
#include <cuda_fp16.h>
#include <cstdint>

// Problem shape (fixed)
#define Bb 4
#define Tt 1024
#define Cc 1024
#define Mm (Bb * Tt)
#define NE (Mm * Cc)
#define WNE (Cc * Cc)

// ---------------------------------------------------------------------------
// Device-global scratch (allocation-free rule)
// ---------------------------------------------------------------------------
__device__ __half g_mk_h[NE], g_mk_l[NE];
__device__ __half g_mv_h[NE];
__device__ __half g_mr_h[NE];
__device__ __half g_at_h[NE], g_at_l[NE];
__device__ __half g_w[4 * WNE];
__device__ float g_k[NE], g_v[NE], g_r[NE];

// ---------------------------------------------------------------------------
// PTX helpers (plain sm_80+ features only)
// ---------------------------------------------------------------------------
__device__ __forceinline__ uint32_t smem_u32(const void* p) {
    uint32_t a;
    asm("{ .reg .u64 t; cvta.to.shared.u64 t, %1; cvt.u32.u64 %0, t; }"
        : "=r"(a) : "l"(p));
    return a;
}

#define CP_ASYNC16(dst, src) \
    asm volatile("cp.async.cg.shared.global [%0], [%1], 16;" \
        :: "r"(dst), "l"(src) : "memory")
#define CP_COMMIT() asm volatile("cp.async.commit_group;" ::: "memory")
#define CP_WAIT0()  asm volatile("cp.async.wait_group 0;" ::: "memory")
#define CP_WAIT1()  asm volatile("cp.async.wait_group 1;" ::: "memory")

__device__ __forceinline__ void ldsm_x4(uint32_t* r, uint32_t addr) {
    asm volatile("ldmatrix.sync.aligned.m8n8.x4.shared.b16 {%0,%1,%2,%3}, [%4];"
        : "=r"(r[0]), "=r"(r[1]), "=r"(r[2]), "=r"(r[3]) : "r"(addr));
}

__device__ __forceinline__ void mma16816(float* c, const uint32_t* a,
                                         uint32_t b0, uint32_t b1) {
    asm volatile(
        "mma.sync.aligned.m16n8k16.row.col.f32.f16.f16.f32 "
        "{%0,%1,%2,%3}, {%4,%5,%6,%7}, {%8,%9}, {%0,%1,%2,%3};"
        : "+f"(c[0]), "+f"(c[1]), "+f"(c[2]), "+f"(c[3])
        : "r"(a[0]), "r"(a[1]), "r"(a[2]), "r"(a[3]), "r"(b0), "r"(b1));
}

// ---------------------------------------------------------------------------
// fp16 conversion helpers
// ---------------------------------------------------------------------------
__device__ __forceinline__ void split4h(float4 m, __half* Hb, __half* Lb,
                                        size_t e0) {
    __half h[4], l[4];
    float mv[4] = {m.x, m.y, m.z, m.w};
#pragma unroll
    for (int i = 0; i < 4; i++) {
        h[i] = __float2half_rn(mv[i]);
        l[i] = __float2half_rn(mv[i] - __half2float(h[i]));
    }
    *(uint2*)(Hb + e0) = *(uint2*)h;
    *(uint2*)(Lb + e0) = *(uint2*)l;
}

__device__ __forceinline__ void cvt4h(float4 m, __half* Hb, size_t e0) {
    __half h[4] = { __float2half_rn(m.x), __float2half_rn(m.y),
                    __float2half_rn(m.z), __float2half_rn(m.w) };
    *(uint2*)(Hb + e0) = *(uint2*)h;
}

// ---------------------------------------------------------------------------
// Kernel 1: time-shift + mix + fp16 conversion
// k path: hi/lo split (exp-sensitive); v, r paths: single fp16
// ---------------------------------------------------------------------------
__global__ __launch_bounds__(256) void mix_kernel(
    const float* __restrict__ X,
    const float* __restrict__ tmk,
    const float* __restrict__ tmv,
    const float* __restrict__ tmr)
{
    int i = blockIdx.x * 256 + threadIdx.x;   // float4 index
    const int PR = Cc / 4;
    int m  = i / PR;
    int c4 = i - m * PR;

    const float4* X4 = (const float4*)X;
    float4 x  = X4[i];
    float4 xp = make_float4(0.f, 0.f, 0.f, 0.f);
    if ((m & (Tt - 1)) != 0) xp = X4[i - PR];

    float4 k4 = ((const float4*)tmk)[c4];
    float4 v4 = ((const float4*)tmv)[c4];
    float4 r4 = ((const float4*)tmr)[c4];

    size_t e0 = (size_t)i * 4;
    float4 o;
    o.x = fmaf(x.x - xp.x, k4.x, xp.x); o.y = fmaf(x.y - xp.y, k4.y, xp.y);
    o.z = fmaf(x.z - xp.z, k4.z, xp.z); o.w = fmaf(x.w - xp.w, k4.w, xp.w);
    split4h(o, g_mk_h, g_mk_l, e0);
    o.x = fmaf(x.x - xp.x, v4.x, xp.x); o.y = fmaf(x.y - xp.y, v4.y, xp.y);
    o.z = fmaf(x.z - xp.z, v4.z, xp.z); o.w = fmaf(x.w - xp.w, v4.w, xp.w);
    cvt4h(o, g_mv_h, e0);
    o.x = fmaf(x.x - xp.x, r4.x, xp.x); o.y = fmaf(x.y - xp.y, r4.y, xp.y);
    o.z = fmaf(x.z - xp.z, r4.z, xp.z); o.w = fmaf(x.w - xp.w, r4.w, xp.w);
    cvt4h(o, g_mr_h, e0);
}

// ---------------------------------------------------------------------------
// Kernel 2: weight fp16 conversion (Wk, Wv, Wr, Wo)
// ---------------------------------------------------------------------------
__global__ __launch_bounds__(256) void wcvt_kernel(
    const float* __restrict__ Wk, const float* __restrict__ Wv,
    const float* __restrict__ Wr, const float* __restrict__ Wo)
{
    int i = blockIdx.x * 256 + threadIdx.x;   // float4 index over 4*WNE/4
    int sel = i >> 18;                        // WNE/4 = 2^18
    int j   = i & ((WNE / 4) - 1);
    const float* W = (sel == 0) ? Wk : (sel == 1) ? Wv : (sel == 2) ? Wr : Wo;
    float4 v = ((const float4*)W)[j];
    cvt4h(v, g_w + (size_t)sel * WNE, (size_t)j * 4);
}

// ---------------------------------------------------------------------------
// fp16 mma.sync GEMM:  C[M,N] = A[M,K] * W[N,K]^T
// DUAL: A = Ah + Al (exact fp16 split), D = Ah*W + Al*W  (k / out paths)
// !DUAL: D = Ah*W  (v / r paths)
// CTA 128x128, BK=32, 256 threads (8 warps, 2m x 4n), warp tile 64x32.
// Double-buffered cp.async smem, padded pitch 40 fp16.
// ---------------------------------------------------------------------------
#define BK 32
#define PITCH 40                       // fp16 elems per smem row (32 + 8 pad)
#define TILE_B (128 * PITCH * 2)       // 10240 B per tile
#define SMEM_GEMM (6 * TILE_B)         // max (dual): 2 stages x 3 tiles
#define NKCH (Cc / BK)                 // 32 chunks

__device__ __forceinline__ void load_tile_async(
    uint32_t sdst, const __half* __restrict__ src,
    int row0, int kt, int tid)
{
#pragma unroll
    for (int i = 0; i < 2; i++) {
        int idx = i * 256 + tid;       // 512 x 16B units
        int r = idx >> 2;
        int c = idx & 3;
        const void* g = src + (size_t)(row0 + r) * Cc + kt * BK + c * 8;
        CP_ASYNC16(sdst + r * (PITCH * 2) + c * 16, g);
    }
}

template <bool DUAL>
__device__ __forceinline__ void gemm_body(
    const __half* __restrict__ Ah, const __half* __restrict__ Al,
    const __half* __restrict__ Wh, float* __restrict__ Cmat)
{
    constexpr uint32_t NT = DUAL ? 3 : 2;       // tiles per stage
    constexpr uint32_t STG = NT * TILE_B;
    extern __shared__ char smem[];
    const uint32_t sb = smem_u32(smem);
    int tid = threadIdx.x;
    int wid = tid >> 5;
    int lid = tid & 31;
    int m0 = blockIdx.y * 128;
    int n0 = blockIdx.x * 128;
    int wm = wid & 1;                  // 2 m-groups of 64 rows
    int wn = wid >> 1;                 // 4 n-groups of 32 cols

    float acc[4][4][4];
#pragma unroll
    for (int a = 0; a < 4; a++)
#pragma unroll
        for (int b = 0; b < 4; b++)
#pragma unroll
            for (int c = 0; c < 4; c++) acc[a][b][c] = 0.f;

    // prologue: chunk 0 -> stage 0
    {
        load_tile_async(sb, Ah, m0, 0, tid);
        if (DUAL) load_tile_async(sb + TILE_B, Al, m0, 0, tid);
        load_tile_async(sb + (NT - 1) * TILE_B, Wh, n0, 0, tid);
        CP_COMMIT();
    }

    for (int kt = 0; kt < NKCH; kt++) {
        int s = kt & 1;
        if (kt + 1 < NKCH) {
            uint32_t st = sb + (s ^ 1) * STG;
            load_tile_async(st, Ah, m0, kt + 1, tid);
            if (DUAL) load_tile_async(st + TILE_B, Al, m0, kt + 1, tid);
            load_tile_async(st + (NT - 1) * TILE_B, Wh, n0, kt + 1, tid);
            CP_COMMIT();
            CP_WAIT1();
        } else {
            CP_WAIT0();
        }
        __syncthreads();

        uint32_t sa  = sb + s * STG;
        uint32_t sAh = sa;
        uint32_t sAl = sa + TILE_B;
        uint32_t sWh = sa + (NT - 1) * TILE_B;

#pragma unroll
        for (int ks = 0; ks < 2; ks++) {
            int koff = ks * 16 + (lid >> 4) * 8;    // elems
            uint32_t ah[4][4], al[4][4];
#pragma unroll
            for (int mi = 0; mi < 4; mi++) {
                int row = wm * 64 + mi * 16 + (lid & 15);
                uint32_t off = (uint32_t)(row * (PITCH * 2) + koff * 2);
                ldsm_x4(ah[mi], sAh + off);
                if (DUAL) ldsm_x4(al[mi], sAl + off);
            }
            uint32_t wh[2][4];
#pragma unroll
            for (int j2 = 0; j2 < 2; j2++) {
                int nrow = wn * 32 + j2 * 16 + (lid & 15);
                uint32_t off = (uint32_t)(nrow * (PITCH * 2) + koff * 2);
                ldsm_x4(wh[j2], sWh + off);
            }
#pragma unroll
            for (int mi = 0; mi < 4; mi++) {
#pragma unroll
                for (int j = 0; j < 4; j++) {
                    uint32_t b0 = wh[j >> 1][j & 1];
                    uint32_t b1 = wh[j >> 1][(j & 1) + 2];
                    mma16816(acc[mi][j], ah[mi], b0, b1);
                    if (DUAL) mma16816(acc[mi][j], al[mi], b0, b1);
                }
            }
        }
        __syncthreads();
    }

    // epilogue
#pragma unroll
    for (int mi = 0; mi < 4; mi++) {
        int m = m0 + wm * 64 + mi * 16 + (lid >> 2);
#pragma unroll
        for (int j = 0; j < 4; j++) {
            int n = n0 + wn * 32 + j * 8 + (lid & 3) * 2;
            *(float2*)(Cmat + (size_t)m * Cc + n) =
                make_float2(acc[mi][j][0], acc[mi][j][1]);
            *(float2*)(Cmat + (size_t)(m + 8) * Cc + n) =
                make_float2(acc[mi][j][2], acc[mi][j][3]);
        }
    }
}

__global__ __launch_bounds__(256) void gemm_kvr(void)
{
    if (blockIdx.z == 0)
        gemm_body<true >(g_mk_h, g_mk_l, g_w,           g_k);
    else if (blockIdx.z == 1)
        gemm_body<false>(g_mv_h, nullptr, g_w + WNE,     g_v);
    else
        gemm_body<false>(g_mr_h, nullptr, g_w + 2 * WNE, g_r);
}

__global__ __launch_bounds__(256) void gemm_out(float* __restrict__ out)
{
    gemm_body<true>(g_at_h, g_at_l, g_w + 3 * WNE, out);
}

// ---------------------------------------------------------------------------
// Kernel 3: WKV recurrence (chunked 2-pass scan) -> att fp16 hi/lo
// Block = 16 channels x 64 chunks (1024 threads), grid (Cc/16, Bb) = 256 CTAs.
// ---------------------------------------------------------------------------
#define SCHUNKS 64
#define SGRP 16
#define SL (Tt / SCHUNKS)              // 16 timesteps per chunk

__global__ __launch_bounds__(1024) void scan_kernel(
    const float* __restrict__ td, const float* __restrict__ tf)
{
    __shared__ float sA[SCHUNKS][SGRP], sB[SCHUNKS][SGRP];
    __shared__ float sAin[SCHUNKS][SGRP], sBin[SCHUNKS][SGRP];

    int g = threadIdx.x & (SGRP - 1);
    int s = threadIdx.x >> 4;
    int c = blockIdx.x * SGRP + g;
    int b = blockIdx.y;

    float E = __expf(td[c]);
    float f = __expf(-E);
    float p = __expf(tf[c]);

    size_t base = ((size_t)b * Tt + s * SL) * Cc + c;

    // Pass 1: local chunk carries (a,b start at 0)
    float aL = 0.f, bL = 0.f;
#pragma unroll 4
    for (int t = 0; t < SL; t++) {
        size_t idx = base + (size_t)t * Cc;
        float kc = __expf(fminf(g_k[idx], 60.f));
        float kv = kc * g_v[idx];
        aL = f * aL + kv;
        bL = f * bL + kc;
    }
    sA[s][g] = aL;
    sB[s][g] = bL;
    __syncthreads();

    // Combine chunk carries (threads 0..SGRP-1)
    if (s == 0) {
        float F = __expf(-E * (float)SL);   // f^SL
        float ain = 0.f, bin = 0.f;
#pragma unroll
        for (int ss = 0; ss < SCHUNKS; ss++) {
            sAin[ss][g] = ain;
            sBin[ss][g] = bin;
            ain = F * ain + sA[ss][g];
            bin = F * bin + sB[ss][g];
        }
    }
    __syncthreads();

    // Pass 2: recompute with correct carry-in, emit att hi/lo (fp16)
    float a  = sAin[s][g];
    float bb = sBin[s][g];
#pragma unroll 4
    for (int t = 0; t < SL; t++) {
        size_t idx = base + (size_t)t * Cc;
        float kc = __expf(fminf(g_k[idx], 60.f));
        float vv = g_v[idx];
        float kv = kc * vv;
        float r  = g_r[idx];
        float sr = 1.f / (1.f + __expf(-r));
        float wkv = p * kv + a;
        float wk  = p * kc + bb + 1e-8f;
        float att = sr * wkv / wk;
        __half h = __float2half_rn(att);
        g_at_h[idx] = h;
        g_at_l[idx] = __float2half_rn(att - __half2float(h));
        a  = f * a  + kv;
        bb = f * bb + kc;
    }
}

// ---------------------------------------------------------------------------
// Launch
// ---------------------------------------------------------------------------
extern "C" void kernel_launch(void* const* d_in, const int* in_sizes, int n_in,
                              void* d_out, int out_size)
{
    const float* xq  = (const float*)d_in[0];
    const float* td  = (const float*)d_in[3];
    const float* tf  = (const float*)d_in[4];
    const float* tmk = (const float*)d_in[5];
    const float* tmv = (const float*)d_in[6];
    const float* tmr = (const float*)d_in[7];
    const float* Wk  = (const float*)d_in[8];
    const float* Wv  = (const float*)d_in[9];
    const float* Wr  = (const float*)d_in[10];
    const float* Wo  = (const float*)d_in[11];
    float* out = (float*)d_out;

    static bool attr_done = false;
    if (!attr_done) {
        cudaFuncSetAttribute(gemm_kvr, cudaFuncAttributeMaxDynamicSharedMemorySize, SMEM_GEMM);
        cudaFuncSetAttribute(gemm_out, cudaFuncAttributeMaxDynamicSharedMemorySize, SMEM_GEMM);
        attr_done = true;
    }

    mix_kernel<<<NE / 4 / 256, 256>>>(xq, tmk, tmv, tmr);
    wcvt_kernel<<<4 * WNE / 4 / 256, 256>>>(Wk, Wv, Wr, Wo);

    dim3 gkvr(Cc / 128, Mm / 128, 3);
    gemm_kvr<<<gkvr, 256, SMEM_GEMM>>>();

    dim3 gscan(Cc / SGRP, Bb, 1);
    scan_kernel<<<gscan, 1024>>>(td, tf);

    dim3 go(Cc / 128, Mm / 128, 1);
    gemm_out<<<go, 256, SMEM_GEMM>>>(out);
}

// round 8
// speedup vs baseline: 1.2333x; 1.2333x over previous
#include <cuda_runtime.h>
#include <cuda_bf16.h>
#include <cuda_fp16.h>
#include <cstdint>

// Problem shape (fixed)
#define Bb 4
#define Tt 1024
#define Cc 1024
#define Mm (Bb * Tt)
#define NE (Mm * Cc)
#define WNE (Cc * Cc)

// ---------------------------------------------------------------------------
// Device-global scratch (allocation-free rule)
// ---------------------------------------------------------------------------
__device__ __half g_mk[NE], g_mv[NE], g_mr[NE];
__device__ __half g_at[NE];
__device__ __half g_w[4 * WNE];
__device__ float g_k[NE], g_v[NE], g_r[NE];

// ---------------------------------------------------------------------------
// PTX helpers (plain sm_80+ features only)
// ---------------------------------------------------------------------------
__device__ __forceinline__ uint32_t smem_u32(const void* p) {
    uint32_t a;
    asm("{ .reg .u64 t; cvta.to.shared.u64 t, %1; cvt.u32.u64 %0, t; }"
        : "=r"(a) : "l"(p));
    return a;
}

#define CP_ASYNC16(dst, src) \
    asm volatile("cp.async.cg.shared.global [%0], [%1], 16;" \
        :: "r"(dst), "l"(src) : "memory")
#define CP_COMMIT() asm volatile("cp.async.commit_group;" ::: "memory")
#define CP_WAIT0()  asm volatile("cp.async.wait_group 0;" ::: "memory")
#define CP_WAIT1()  asm volatile("cp.async.wait_group 1;" ::: "memory")

__device__ __forceinline__ void ldsm_x4(uint32_t* r, uint32_t addr) {
    asm volatile("ldmatrix.sync.aligned.m8n8.x4.shared.b16 {%0,%1,%2,%3}, [%4];"
        : "=r"(r[0]), "=r"(r[1]), "=r"(r[2]), "=r"(r[3]) : "r"(addr));
}

__device__ __forceinline__ void mma16816(float* c, const uint32_t* a,
                                         uint32_t b0, uint32_t b1) {
    asm volatile(
        "mma.sync.aligned.m16n8k16.row.col.f32.f16.f16.f32 "
        "{%0,%1,%2,%3}, {%4,%5,%6,%7}, {%8,%9}, {%0,%1,%2,%3};"
        : "+f"(c[0]), "+f"(c[1]), "+f"(c[2]), "+f"(c[3])
        : "r"(a[0]), "r"(a[1]), "r"(a[2]), "r"(a[3]), "r"(b0), "r"(b1));
}

__device__ __forceinline__ void cvt4h(float4 m, __half* Hb, size_t e0) {
    __half h[4] = { __float2half_rn(m.x), __float2half_rn(m.y),
                    __float2half_rn(m.z), __float2half_rn(m.w) };
    *(uint2*)(Hb + e0) = *(uint2*)h;
}

// ---------------------------------------------------------------------------
// Kernel 1 (merged prep): blocks [0, NE/1024)   -> time-shift + mix -> fp16
//                         blocks [NE/1024, ...) -> weight fp16 conversion
// ---------------------------------------------------------------------------
#define MIX_BLOCKS  (NE / 4 / 256)
#define WCVT_BLOCKS (4 * WNE / 4 / 256)

__global__ __launch_bounds__(256) void prep_kernel(
    const float* __restrict__ X,
    const float* __restrict__ tmk,
    const float* __restrict__ tmv,
    const float* __restrict__ tmr,
    const float* __restrict__ Wk, const float* __restrict__ Wv,
    const float* __restrict__ Wr, const float* __restrict__ Wo)
{
    if (blockIdx.x < MIX_BLOCKS) {
        int i = blockIdx.x * 256 + threadIdx.x;   // float4 index
        const int PR = Cc / 4;
        int m  = i / PR;
        int c4 = i - m * PR;

        const float4* X4 = (const float4*)X;
        float4 x  = X4[i];
        float4 xp = make_float4(0.f, 0.f, 0.f, 0.f);
        if ((m & (Tt - 1)) != 0) xp = X4[i - PR];

        float4 k4 = ((const float4*)tmk)[c4];
        float4 v4 = ((const float4*)tmv)[c4];
        float4 r4 = ((const float4*)tmr)[c4];

        size_t e0 = (size_t)i * 4;
        float4 o;
        o.x = fmaf(x.x - xp.x, k4.x, xp.x); o.y = fmaf(x.y - xp.y, k4.y, xp.y);
        o.z = fmaf(x.z - xp.z, k4.z, xp.z); o.w = fmaf(x.w - xp.w, k4.w, xp.w);
        cvt4h(o, g_mk, e0);
        o.x = fmaf(x.x - xp.x, v4.x, xp.x); o.y = fmaf(x.y - xp.y, v4.y, xp.y);
        o.z = fmaf(x.z - xp.z, v4.z, xp.z); o.w = fmaf(x.w - xp.w, v4.w, xp.w);
        cvt4h(o, g_mv, e0);
        o.x = fmaf(x.x - xp.x, r4.x, xp.x); o.y = fmaf(x.y - xp.y, r4.y, xp.y);
        o.z = fmaf(x.z - xp.z, r4.z, xp.z); o.w = fmaf(x.w - xp.w, r4.w, xp.w);
        cvt4h(o, g_mr, e0);
    } else {
        int i = (blockIdx.x - MIX_BLOCKS) * 256 + threadIdx.x;
        int sel = i >> 18;                        // WNE/4 = 2^18
        int j   = i & ((WNE / 4) - 1);
        const float* W = (sel == 0) ? Wk : (sel == 1) ? Wv
                       : (sel == 2) ? Wr : Wo;
        float4 v = ((const float4*)W)[j];
        cvt4h(v, g_w + (size_t)sel * WNE, (size_t)j * 4);
    }
}

// ---------------------------------------------------------------------------
// fp16 mma.sync GEMM (single product):  C[M,N] = A[M,K] * W[N,K]^T
// CTA 128x128, BK=32, 256 threads (8 warps, 2m x 4n), warp tile 64x32.
// Double-buffered cp.async smem, padded pitch 40 fp16.
// ---------------------------------------------------------------------------
#define BK 32
#define PITCH 40                       // fp16 elems per smem row (32 + 8 pad)
#define TILE_B (128 * PITCH * 2)       // 10240 B per tile
#define STG    (2 * TILE_B)            // A, W per stage
#define SMEM_GEMM (2 * STG)            // 40960 B
#define NKCH (Cc / BK)                 // 32 chunks

__device__ __forceinline__ void load_tile_async(
    uint32_t sdst, const __half* __restrict__ src,
    int row0, int kt, int tid)
{
#pragma unroll
    for (int i = 0; i < 2; i++) {
        int idx = i * 256 + tid;       // 512 x 16B units
        int r = idx >> 2;
        int c = idx & 3;
        const void* g = src + (size_t)(row0 + r) * Cc + kt * BK + c * 8;
        CP_ASYNC16(sdst + r * (PITCH * 2) + c * 16, g);
    }
}

__device__ __forceinline__ void gemm_body(
    const __half* __restrict__ A, const __half* __restrict__ W,
    float* __restrict__ Cmat)
{
    extern __shared__ char smem[];
    const uint32_t sb = smem_u32(smem);
    int tid = threadIdx.x;
    int wid = tid >> 5;
    int lid = tid & 31;
    int m0 = blockIdx.y * 128;
    int n0 = blockIdx.x * 128;
    int wm = wid & 1;                  // 2 m-groups of 64 rows
    int wn = wid >> 1;                 // 4 n-groups of 32 cols

    float acc[4][4][4];
#pragma unroll
    for (int a = 0; a < 4; a++)
#pragma unroll
        for (int b = 0; b < 4; b++)
#pragma unroll
            for (int c = 0; c < 4; c++) acc[a][b][c] = 0.f;

    // prologue: chunk 0 -> stage 0
    load_tile_async(sb,          A, m0, 0, tid);
    load_tile_async(sb + TILE_B, W, n0, 0, tid);
    CP_COMMIT();

    for (int kt = 0; kt < NKCH; kt++) {
        int s = kt & 1;
        if (kt + 1 < NKCH) {
            uint32_t st = sb + (s ^ 1) * STG;
            load_tile_async(st,          A, m0, kt + 1, tid);
            load_tile_async(st + TILE_B, W, n0, kt + 1, tid);
            CP_COMMIT();
            CP_WAIT1();
        } else {
            CP_WAIT0();
        }
        __syncthreads();

        uint32_t sA = sb + s * STG;
        uint32_t sW = sA + TILE_B;

#pragma unroll
        for (int ks = 0; ks < 2; ks++) {
            int koff = ks * 16 + (lid >> 4) * 8;    // elems
            uint32_t af[4][4];
#pragma unroll
            for (int mi = 0; mi < 4; mi++) {
                int row = wm * 64 + mi * 16 + (lid & 15);
                uint32_t off = (uint32_t)(row * (PITCH * 2) + koff * 2);
                ldsm_x4(af[mi], sA + off);
            }
            uint32_t wf[2][4];
#pragma unroll
            for (int j2 = 0; j2 < 2; j2++) {
                int nrow = wn * 32 + j2 * 16 + (lid & 15);
                uint32_t off = (uint32_t)(nrow * (PITCH * 2) + koff * 2);
                ldsm_x4(wf[j2], sW + off);
            }
#pragma unroll
            for (int mi = 0; mi < 4; mi++) {
#pragma unroll
                for (int j = 0; j < 4; j++) {
                    uint32_t b0 = wf[j >> 1][j & 1];
                    uint32_t b1 = wf[j >> 1][(j & 1) + 2];
                    mma16816(acc[mi][j], af[mi], b0, b1);
                }
            }
        }
        __syncthreads();
    }

    // epilogue
#pragma unroll
    for (int mi = 0; mi < 4; mi++) {
        int m = m0 + wm * 64 + mi * 16 + (lid >> 2);
#pragma unroll
        for (int j = 0; j < 4; j++) {
            int n = n0 + wn * 32 + j * 8 + (lid & 3) * 2;
            *(float2*)(Cmat + (size_t)m * Cc + n) =
                make_float2(acc[mi][j][0], acc[mi][j][1]);
            *(float2*)(Cmat + (size_t)(m + 8) * Cc + n) =
                make_float2(acc[mi][j][2], acc[mi][j][3]);
        }
    }
}

__global__ __launch_bounds__(256) void gemm_kvr(void)
{
    if (blockIdx.z == 0)
        gemm_body(g_mk, g_w,           g_k);
    else if (blockIdx.z == 1)
        gemm_body(g_mv, g_w + WNE,     g_v);
    else
        gemm_body(g_mr, g_w + 2 * WNE, g_r);
}

__global__ __launch_bounds__(256) void gemm_out(float* __restrict__ out)
{
    gemm_body(g_at, g_w + 3 * WNE, out);
}

// ---------------------------------------------------------------------------
// Kernel 3: WKV recurrence (chunked 2-pass scan) -> att fp16
// Block = 16 channels x 64 chunks (1024 threads), grid (Cc/16, Bb) = 256 CTAs.
// Pass-1 values (kc, kv) cached in registers; pass 2 only reads r.
// ---------------------------------------------------------------------------
#define SCHUNKS 64
#define SGRP 16
#define SL (Tt / SCHUNKS)              // 16 timesteps per chunk

__global__ __launch_bounds__(1024) void scan_kernel(
    const float* __restrict__ td, const float* __restrict__ tf)
{
    __shared__ float sA[SCHUNKS][SGRP], sB[SCHUNKS][SGRP];
    __shared__ float sAin[SCHUNKS][SGRP], sBin[SCHUNKS][SGRP];

    int g = threadIdx.x & (SGRP - 1);
    int s = threadIdx.x >> 4;
    int c = blockIdx.x * SGRP + g;
    int b = blockIdx.y;

    float E = __expf(td[c]);
    float f = __expf(-E);
    float p = __expf(tf[c]);

    size_t base = ((size_t)b * Tt + s * SL) * Cc + c;

    // Pass 1: local chunk carries; cache kc/kv in registers
    float kcR[SL], kvR[SL];
    float aL = 0.f, bL = 0.f;
#pragma unroll
    for (int t = 0; t < SL; t++) {
        size_t idx = base + (size_t)t * Cc;
        float kc = __expf(fminf(g_k[idx], 60.f));
        float kv = kc * g_v[idx];
        kcR[t] = kc;
        kvR[t] = kv;
        aL = f * aL + kv;
        bL = f * bL + kc;
    }
    sA[s][g] = aL;
    sB[s][g] = bL;
    __syncthreads();

    // Combine chunk carries (threads 0..SGRP-1)
    if (s == 0) {
        float F = __expf(-E * (float)SL);   // f^SL
        float ain = 0.f, bin = 0.f;
#pragma unroll
        for (int ss = 0; ss < SCHUNKS; ss++) {
            sAin[ss][g] = ain;
            sBin[ss][g] = bin;
            ain = F * ain + sA[ss][g];
            bin = F * bin + sB[ss][g];
        }
    }
    __syncthreads();

    // Pass 2: emit att (fp16) using cached kc/kv + correct carry-in
    float a  = sAin[s][g];
    float bb = sBin[s][g];
#pragma unroll
    for (int t = 0; t < SL; t++) {
        size_t idx = base + (size_t)t * Cc;
        float kc = kcR[t];
        float kv = kvR[t];
        float r  = g_r[idx];
        float sr = 1.f / (1.f + __expf(-r));
        float wkv = p * kv + a;
        float wk  = p * kc + bb + 1e-8f;
        g_at[idx] = __float2half_rn(sr * wkv / wk);
        a  = f * a  + kv;
        bb = f * bb + kc;
    }
}

// ---------------------------------------------------------------------------
// Launch
// ---------------------------------------------------------------------------
extern "C" void kernel_launch(void* const* d_in, const int* in_sizes, int n_in,
                              void* d_out, int out_size)
{
    const float* xq  = (const float*)d_in[0];
    const float* td  = (const float*)d_in[3];
    const float* tf  = (const float*)d_in[4];
    const float* tmk = (const float*)d_in[5];
    const float* tmv = (const float*)d_in[6];
    const float* tmr = (const float*)d_in[7];
    const float* Wk  = (const float*)d_in[8];
    const float* Wv  = (const float*)d_in[9];
    const float* Wr  = (const float*)d_in[10];
    const float* Wo  = (const float*)d_in[11];
    float* out = (float*)d_out;

    static bool attr_done = false;
    if (!attr_done) {
        cudaFuncSetAttribute(gemm_kvr, cudaFuncAttributeMaxDynamicSharedMemorySize, SMEM_GEMM);
        cudaFuncSetAttribute(gemm_out, cudaFuncAttributeMaxDynamicSharedMemorySize, SMEM_GEMM);
        attr_done = true;
    }

    prep_kernel<<<MIX_BLOCKS + WCVT_BLOCKS, 256>>>(
        xq, tmk, tmv, tmr, Wk, Wv, Wr, Wo);

    dim3 gkvr(Cc / 128, Mm / 128, 3);
    gemm_kvr<<<gkvr, 256, SMEM_GEMM>>>();

    dim3 gscan(Cc / SGRP, Bb, 1);
    scan_kernel<<<gscan, 1024>>>(td, tf);

    dim3 go(Cc / 128, Mm / 128, 1);
    gemm_out<<<go, 256, SMEM_GEMM>>>(out);
}

// round 10
// speedup vs baseline: 1.4517x; 1.1771x over previous
#include <cuda_runtime.h>
#include <cuda_bf16.h>
#include <cuda_fp16.h>
#include <cstdint>

// Problem shape (fixed)
#define Bb 4
#define Tt 1024
#define Cc 1024
#define Mm (Bb * Tt)
#define NE (Mm * Cc)
#define WNE (Cc * Cc)

// ---------------------------------------------------------------------------
// Device-global scratch (allocation-free rule)
// ---------------------------------------------------------------------------
__device__ __half g_mk[NE], g_mv[NE], g_mr[NE];
__device__ __half g_at[NE];
__device__ __half g_w[4 * WNE];
__device__ float g_k[NE], g_v[NE], g_r[NE];

// ---------------------------------------------------------------------------
// PTX helpers (plain sm_80+ features only)
// ---------------------------------------------------------------------------
__device__ __forceinline__ uint32_t smem_u32(const void* p) {
    uint32_t a;
    asm("{ .reg .u64 t; cvta.to.shared.u64 t, %1; cvt.u32.u64 %0, t; }"
        : "=r"(a) : "l"(p));
    return a;
}

#define CP_ASYNC16(dst, src) \
    asm volatile("cp.async.cg.shared.global [%0], [%1], 16;" \
        :: "r"(dst), "l"(src) : "memory")
#define CP_COMMIT() asm volatile("cp.async.commit_group;" ::: "memory")
#define CP_WAIT0()  asm volatile("cp.async.wait_group 0;" ::: "memory")
#define CP_WAIT1()  asm volatile("cp.async.wait_group 1;" ::: "memory")

__device__ __forceinline__ void ldsm_x4(uint32_t* r, uint32_t addr) {
    asm volatile("ldmatrix.sync.aligned.m8n8.x4.shared.b16 {%0,%1,%2,%3}, [%4];"
        : "=r"(r[0]), "=r"(r[1]), "=r"(r[2]), "=r"(r[3]) : "r"(addr));
}

__device__ __forceinline__ void mma16816(float* c, const uint32_t* a,
                                         uint32_t b0, uint32_t b1) {
    asm volatile(
        "mma.sync.aligned.m16n8k16.row.col.f32.f16.f16.f32 "
        "{%0,%1,%2,%3}, {%4,%5,%6,%7}, {%8,%9}, {%0,%1,%2,%3};"
        : "+f"(c[0]), "+f"(c[1]), "+f"(c[2]), "+f"(c[3])
        : "r"(a[0]), "r"(a[1]), "r"(a[2]), "r"(a[3]), "r"(b0), "r"(b1));
}

__device__ __forceinline__ void cvt4h(float4 m, __half* Hb, size_t e0) {
    __half h[4] = { __float2half_rn(m.x), __float2half_rn(m.y),
                    __float2half_rn(m.z), __float2half_rn(m.w) };
    *(uint2*)(Hb + e0) = *(uint2*)h;
}

// ---------------------------------------------------------------------------
// Kernel 1 (merged prep): blocks [0, MIX_BLOCKS)  -> time-shift + mix -> fp16
//                         blocks [MIX_BLOCKS, ..) -> weight fp16 conversion
// ---------------------------------------------------------------------------
#define MIX_BLOCKS  (NE / 4 / 256)
#define WCVT_BLOCKS (4 * WNE / 4 / 256)

__global__ __launch_bounds__(256) void prep_kernel(
    const float* __restrict__ X,
    const float* __restrict__ tmk,
    const float* __restrict__ tmv,
    const float* __restrict__ tmr,
    const float* __restrict__ Wk, const float* __restrict__ Wv,
    const float* __restrict__ Wr, const float* __restrict__ Wo)
{
    if (blockIdx.x < MIX_BLOCKS) {
        int i = blockIdx.x * 256 + threadIdx.x;   // float4 index
        const int PR = Cc / 4;
        int m  = i / PR;
        int c4 = i - m * PR;

        const float4* X4 = (const float4*)X;
        float4 x  = X4[i];
        float4 xp = make_float4(0.f, 0.f, 0.f, 0.f);
        if ((m & (Tt - 1)) != 0) xp = X4[i - PR];

        float4 k4 = ((const float4*)tmk)[c4];
        float4 v4 = ((const float4*)tmv)[c4];
        float4 r4 = ((const float4*)tmr)[c4];

        size_t e0 = (size_t)i * 4;
        float4 o;
        o.x = fmaf(x.x - xp.x, k4.x, xp.x); o.y = fmaf(x.y - xp.y, k4.y, xp.y);
        o.z = fmaf(x.z - xp.z, k4.z, xp.z); o.w = fmaf(x.w - xp.w, k4.w, xp.w);
        cvt4h(o, g_mk, e0);
        o.x = fmaf(x.x - xp.x, v4.x, xp.x); o.y = fmaf(x.y - xp.y, v4.y, xp.y);
        o.z = fmaf(x.z - xp.z, v4.z, xp.z); o.w = fmaf(x.w - xp.w, v4.w, xp.w);
        cvt4h(o, g_mv, e0);
        o.x = fmaf(x.x - xp.x, r4.x, xp.x); o.y = fmaf(x.y - xp.y, r4.y, xp.y);
        o.z = fmaf(x.z - xp.z, r4.z, xp.z); o.w = fmaf(x.w - xp.w, r4.w, xp.w);
        cvt4h(o, g_mr, e0);
    } else {
        int i = (blockIdx.x - MIX_BLOCKS) * 256 + threadIdx.x;
        int sel = i >> 18;                        // WNE/4 = 2^18
        int j   = i & ((WNE / 4) - 1);
        const float* W = (sel == 0) ? Wk : (sel == 1) ? Wv
                       : (sel == 2) ? Wr : Wo;
        float4 v = ((const float4*)W)[j];
        cvt4h(v, g_w + (size_t)sel * WNE, (size_t)j * 4);
    }
}

// ---------------------------------------------------------------------------
// fp16 mma.sync GEMM (single product):  C[M,N] = A[M,K] * W[N,K]^T
// CTA 128x128, BK=32, 512 threads (16 warps, 4m x 4n), warp tile 32x32.
// 3-stage cp.async pipeline (loads 2 chunks ahead), one barrier per chunk.
// ---------------------------------------------------------------------------
#define BK 32
#define PITCH 40                       // fp16 elems per smem row (32 + 8 pad)
#define TILE_B (128 * PITCH * 2)       // 10240 B per tile
#define STG    (2 * TILE_B)            // A, W per stage
#define NSTAGE 3
#define SMEM_GEMM (NSTAGE * STG)       // 61440 B
#define NKCH (Cc / BK)                 // 32 chunks

// 512 threads x one 16B unit = a full 128x32 fp16 tile
__device__ __forceinline__ void load_stage_async(
    uint32_t sdst, const __half* __restrict__ A, int m0,
    const __half* __restrict__ W, int n0, int kt, int tid)
{
    int r = tid >> 2;
    int c = tid & 3;
    uint32_t so = (uint32_t)(r * (PITCH * 2) + c * 16);
    size_t go = (size_t)r * Cc + (size_t)kt * BK + c * 8;
    CP_ASYNC16(sdst + so,          (const void*)(A + (size_t)m0 * Cc + go));
    CP_ASYNC16(sdst + TILE_B + so, (const void*)(W + (size_t)n0 * Cc + go));
}

__device__ __forceinline__ void gemm_body(
    const __half* __restrict__ A, const __half* __restrict__ W,
    float* __restrict__ Cmat)
{
    extern __shared__ char smem[];
    const uint32_t sb = smem_u32(smem);
    int tid = threadIdx.x;
    int wid = tid >> 5;
    int lid = tid & 31;
    int m0 = blockIdx.y * 128;
    int n0 = blockIdx.x * 128;
    int wm = wid & 3;                  // 4 m-groups of 32 rows
    int wn = wid >> 2;                 // 4 n-groups of 32 cols

    float acc[2][4][4];
#pragma unroll
    for (int a = 0; a < 2; a++)
#pragma unroll
        for (int b = 0; b < 4; b++)
#pragma unroll
            for (int c = 0; c < 4; c++) acc[a][b][c] = 0.f;

    // prologue: chunks 0,1 -> stages 0,1
    load_stage_async(sb,       A, m0, W, n0, 0, tid);
    CP_COMMIT();
    load_stage_async(sb + STG, A, m0, W, n0, 1, tid);
    CP_COMMIT();

    for (int kt = 0; kt < NKCH; kt++) {
        if (kt + 2 < NKCH) CP_WAIT1(); else CP_WAIT0();
        __syncthreads();               // stage kt ready; all warps done kt-1

        if (kt + 2 < NKCH) {
            // stage (kt+2)%3 was consumed in chunk kt-1 -> safe to overwrite
            load_stage_async(sb + ((kt + 2) % NSTAGE) * STG,
                             A, m0, W, n0, kt + 2, tid);
            CP_COMMIT();
        }

        uint32_t sA = sb + (kt % NSTAGE) * STG;
        uint32_t sW = sA + TILE_B;

#pragma unroll
        for (int ks = 0; ks < 2; ks++) {
            int koff = ks * 16 + (lid >> 4) * 8;    // elems
            uint32_t af[2][4];
#pragma unroll
            for (int mi = 0; mi < 2; mi++) {
                int row = wm * 32 + mi * 16 + (lid & 15);
                ldsm_x4(af[mi], sA + (uint32_t)(row * (PITCH * 2) + koff * 2));
            }
            uint32_t wf[2][4];
#pragma unroll
            for (int j2 = 0; j2 < 2; j2++) {
                int nrow = wn * 32 + j2 * 16 + (lid & 15);
                ldsm_x4(wf[j2], sW + (uint32_t)(nrow * (PITCH * 2) + koff * 2));
            }
#pragma unroll
            for (int mi = 0; mi < 2; mi++) {
#pragma unroll
                for (int j = 0; j < 4; j++) {
                    uint32_t b0 = wf[j >> 1][j & 1];
                    uint32_t b1 = wf[j >> 1][(j & 1) + 2];
                    mma16816(acc[mi][j], af[mi], b0, b1);
                }
            }
        }
    }

    // epilogue
#pragma unroll
    for (int mi = 0; mi < 2; mi++) {
        int m = m0 + wm * 32 + mi * 16 + (lid >> 2);
#pragma unroll
        for (int j = 0; j < 4; j++) {
            int n = n0 + wn * 32 + j * 8 + (lid & 3) * 2;
            *(float2*)(Cmat + (size_t)m * Cc + n) =
                make_float2(acc[mi][j][0], acc[mi][j][1]);
            *(float2*)(Cmat + (size_t)(m + 8) * Cc + n) =
                make_float2(acc[mi][j][2], acc[mi][j][3]);
        }
    }
}

__global__ __launch_bounds__(512) void gemm_kvr(void)
{
    if (blockIdx.z == 0)
        gemm_body(g_mk, g_w,           g_k);
    else if (blockIdx.z == 1)
        gemm_body(g_mv, g_w + WNE,     g_v);
    else
        gemm_body(g_mr, g_w + 2 * WNE, g_r);
}

__global__ __launch_bounds__(512) void gemm_out(float* __restrict__ out)
{
    gemm_body(g_at, g_w + 3 * WNE, out);
}

// ---------------------------------------------------------------------------
// Kernel 3: WKV recurrence (chunked 2-pass scan) -> att fp16
// Block = 16 channels x 64 chunks (1024 threads), grid (Cc/16, Bb) = 256 CTAs.
// Pass-1 values (kc, kv) cached in registers; pass 2 only reads r.
// ---------------------------------------------------------------------------
#define SCHUNKS 64
#define SGRP 16
#define SL (Tt / SCHUNKS)              // 16 timesteps per chunk

__global__ __launch_bounds__(1024) void scan_kernel(
    const float* __restrict__ td, const float* __restrict__ tf)
{
    __shared__ float sA[SCHUNKS][SGRP], sB[SCHUNKS][SGRP];
    __shared__ float sAin[SCHUNKS][SGRP], sBin[SCHUNKS][SGRP];

    int g = threadIdx.x & (SGRP - 1);
    int s = threadIdx.x >> 4;
    int c = blockIdx.x * SGRP + g;
    int b = blockIdx.y;

    float E = __expf(td[c]);
    float f = __expf(-E);
    float p = __expf(tf[c]);

    size_t base = ((size_t)b * Tt + s * SL) * Cc + c;

    // Pass 1: local chunk carries; cache kc/kv in registers
    float kcR[SL], kvR[SL];
    float aL = 0.f, bL = 0.f;
#pragma unroll
    for (int t = 0; t < SL; t++) {
        size_t idx = base + (size_t)t * Cc;
        float kc = __expf(fminf(g_k[idx], 60.f));
        float kv = kc * g_v[idx];
        kcR[t] = kc;
        kvR[t] = kv;
        aL = f * aL + kv;
        bL = f * bL + kc;
    }
    sA[s][g] = aL;
    sB[s][g] = bL;
    __syncthreads();

    // Combine chunk carries (threads 0..SGRP-1)
    if (s == 0) {
        float F = __expf(-E * (float)SL);   // f^SL
        float ain = 0.f, bin = 0.f;
#pragma unroll
        for (int ss = 0; ss < SCHUNKS; ss++) {
            sAin[ss][g] = ain;
            sBin[ss][g] = bin;
            ain = F * ain + sA[ss][g];
            bin = F * bin + sB[ss][g];
        }
    }
    __syncthreads();

    // Pass 2: emit att (fp16) using cached kc/kv + correct carry-in
    float a  = sAin[s][g];
    float bb = sBin[s][g];
#pragma unroll
    for (int t = 0; t < SL; t++) {
        size_t idx = base + (size_t)t * Cc;
        float kc = kcR[t];
        float kv = kvR[t];
        float r  = g_r[idx];
        float sr = 1.f / (1.f + __expf(-r));
        float wkv = p * kv + a;
        float wk  = p * kc + bb + 1e-8f;
        g_at[idx] = __float2half_rn(sr * wkv / wk);
        a  = f * a  + kv;
        bb = f * bb + kc;
    }
}

// ---------------------------------------------------------------------------
// Launch
// ---------------------------------------------------------------------------
extern "C" void kernel_launch(void* const* d_in, const int* in_sizes, int n_in,
                              void* d_out, int out_size)
{
    const float* xq  = (const float*)d_in[0];
    const float* td  = (const float*)d_in[3];
    const float* tf  = (const float*)d_in[4];
    const float* tmk = (const float*)d_in[5];
    const float* tmv = (const float*)d_in[6];
    const float* tmr = (const float*)d_in[7];
    const float* Wk  = (const float*)d_in[8];
    const float* Wv  = (const float*)d_in[9];
    const float* Wr  = (const float*)d_in[10];
    const float* Wo  = (const float*)d_in[11];
    float* out = (float*)d_out;

    static bool attr_done = false;
    if (!attr_done) {
        cudaFuncSetAttribute(gemm_kvr, cudaFuncAttributeMaxDynamicSharedMemorySize, SMEM_GEMM);
        cudaFuncSetAttribute(gemm_out, cudaFuncAttributeMaxDynamicSharedMemorySize, SMEM_GEMM);
        attr_done = true;
    }

    prep_kernel<<<MIX_BLOCKS + WCVT_BLOCKS, 256>>>(
        xq, tmk, tmv, tmr, Wk, Wv, Wr, Wo);

    dim3 gkvr(Cc / 128, Mm / 128, 3);
    gemm_kvr<<<gkvr, 512, SMEM_GEMM>>>();

    dim3 gscan(Cc / SGRP, Bb, 1);
    scan_kernel<<<gscan, 1024>>>(td, tf);

    dim3 go(Cc / 128, Mm / 128, 1);
    gemm_out<<<go, 512, SMEM_GEMM>>>(out);
}